// round 15
// baseline (speedup 1.0000x reference)
#include <cuda_runtime.h>
#include <cuda_fp16.h>
#include <cstdint>

// ---------------------------------------------------------------------------
// CausalVAE2: B=262144, D=64, HID=256
// out layout: [x_out B*64][mu B*64][log_var B*64][y_recon B*128]
// Encoder + decoder on mma.sync fp16 (1-term). Decoder v7: paired i <-> 63-i
// per CTA (kmax_a + kmax_b == 5 always), shared A tiles, MMA-ized epilogue.
// ---------------------------------------------------------------------------

#define BATCH 262144
#define DD 64
#define HID 256
#define NT256 (BATCH / 256)           // 1024 row tiles of 256

// Scratch (device globals)
__device__ __align__(16) unsigned char g_abf[(size_t)BATCH * 128];  // 32MB eps_y fp16 [row][64k]
__device__ __align__(16) unsigned char g_xf16[(size_t)BATCH * 128]; // 32MB x fp16 [row][64k]
__device__ __align__(16) unsigned char g_wbf[(size_t)DD * 32768];   // 2MB dec W' [n][k] fp16
__device__ __align__(16) unsigned char g_ew1[256 * 128];            // enc W1 B-layout fp16
__device__ __align__(16) unsigned char g_ew2[128 * 512];            // enc W2 B-layout fp16
__device__ int g_mask[DD * DD];

// ---- baseline tensor-core primitives --------------------------------------
static __device__ __forceinline__ uint32_t smem_u32(const void* p) {
    uint32_t a;
    asm("{ .reg .u64 t; cvta.to.shared.u64 t, %1; cvt.u32.u64 %0, t; }" : "=r"(a) : "l"(p));
    return a;
}
static __device__ __forceinline__ void ldsm_x4(uint32_t addr, uint32_t& r0, uint32_t& r1,
                                               uint32_t& r2, uint32_t& r3) {
    asm volatile("ldmatrix.sync.aligned.m8n8.x4.shared.b16 {%0,%1,%2,%3}, [%4];"
                 : "=r"(r0), "=r"(r1), "=r"(r2), "=r"(r3) : "r"(addr));
}
static __device__ __forceinline__ void mma16816(float* d, const uint32_t* a,
                                                uint32_t b0, uint32_t b1) {
    asm volatile("mma.sync.aligned.m16n8k16.row.col.f32.f16.f16.f32 "
                 "{%0,%1,%2,%3}, {%4,%5,%6,%7}, {%8,%9}, {%0,%1,%2,%3};"
                 : "+f"(d[0]), "+f"(d[1]), "+f"(d[2]), "+f"(d[3])
                 : "r"(a[0]), "r"(a[1]), "r"(a[2]), "r"(a[3]), "r"(b0), "r"(b1));
}
static __device__ __forceinline__ void cp_async16(uint32_t dst, const void* src) {
    asm volatile("cp.async.cg.shared.global [%0], [%1], 16;" :: "r"(dst), "l"(src));
}
#define CP_COMMIT() asm volatile("cp.async.commit_group;" ::: "memory")
#define CP_WAIT0()  asm volatile("cp.async.wait_group 0;" ::: "memory")

extern __shared__ __align__(1024) char smemraw[];

// ---------------------------------------------------------------------------
// Mask decode (robust to bool delivered as u8 / i32 / f32)
// ---------------------------------------------------------------------------
__global__ void mask_expand_kernel(const unsigned char* __restrict__ mb) {
    __shared__ int flags[2];
    __shared__ int s_mode;
    int tid = threadIdx.x;
    if (tid < 2) flags[tid] = 0;
    __syncthreads();
    for (int idx = tid; idx < DD * DD; idx += blockDim.x) {
        unsigned char b = mb[idx];
        if ((idx & 3) != 0 && b != 0) {
            atomicOr(&flags[1], 1);
            if (b > 1) atomicOr(&flags[0], 1);
        }
    }
    __syncthreads();
    if (tid == 0) s_mode = flags[0] ? 2 : (flags[1] ? 1 : 0);
    __syncthreads();
    int mode = s_mode;
    for (int idx = tid; idx < DD * DD; idx += blockDim.x) {
        int v;
        if (mode == 2)      v = (((const float*)mb)[idx] != 0.0f);
        else if (mode == 1) v = (mb[idx] != 0);
        else                v = (((const int*)mb)[idx] != 0);
        g_mask[idx] = v;
    }
}

// ---------------------------------------------------------------------------
// Decoder W-prep: masked dec1_w -> fp16, layout [n][k].
// ---------------------------------------------------------------------------
__global__ void wprep_kernel(const float* __restrict__ w1g) {
    int i = blockIdx.x, tid = threadIdx.x;
    unsigned char* wb = g_wbf + (size_t)i * 32768;
    for (int idx = tid; idx < DD * HID; idx += blockDim.x) {
        int k = idx >> 8, n = idx & 255;
        float m = (float)g_mask[k * DD + i];
        float w = w1g[(size_t)i * DD * HID + (size_t)k * HID + n] * m;
        *(__half*)(wb + n * 128 + k * 2) = __float2half_rn(w);
    }
}

// ---------------------------------------------------------------------------
// Encoder W-prep: enc1_w -> [n][k]; enc3_w -> [n][k]. fp16.
// ---------------------------------------------------------------------------
__global__ void ewprep_kernel(const float* __restrict__ w1,
                              const float* __restrict__ w2) {
    int t = blockIdx.x * 256 + threadIdx.x;
    int stride = gridDim.x * 256;
    for (int idx = t; idx < 64 * 256; idx += stride) {
        int n = idx >> 6, k = idx & 63;
        *(__half*)(g_ew1 + n * 128 + k * 2) = __float2half_rn(w1[k * 256 + n]);
    }
    for (int idx = t; idx < 256 * 128; idx += stride) {
        int n = idx >> 8, k = idx & 255;
        *(__half*)(g_ew2 + n * 512 + k * 2) = __float2half_rn(w2[k * 128 + n]);
    }
}

// ---------------------------------------------------------------------------
// x fp32 -> fp16 rows [row][64k]
// ---------------------------------------------------------------------------
__global__ void xprep_kernel(const float2* __restrict__ x) {
    size_t idx = (size_t)blockIdx.x * blockDim.x + threadIdx.x;
    float2 v = x[idx];
    ((__half2*)g_xf16)[idx] = __floats2half2_rn(v.x, v.y);
}

// ---------------------------------------------------------------------------
// Tensor-core fused encoder (R13, unchanged).
// ---------------------------------------------------------------------------
#define E_SB1 0
#define E_SB2 1024
#define E_SW1 1536
#define E_SW2 38400
#define E_SX  105984
#define E_SH  142848

__global__ __launch_bounds__(256, 1)
void enc_mma_kernel(const float* __restrict__ eps,
                    const float* __restrict__ b1g,
                    const float* __restrict__ b2g,
                    float* __restrict__ outMu,
                    float* __restrict__ outLv) {
    uint32_t sb = smem_u32(smemraw);
    float* sB1e = (float*)(smemraw + E_SB1);
    float* sB2e = (float*)(smemraw + E_SB2);
    int tid = threadIdx.x, wid = tid >> 5, lane = tid & 31;
    int row0 = blockIdx.x * 256;
    int r8 = lane & 7, g = lane >> 3;
    int mt = wid & 3, nh = wid >> 2;
    int cq = (lane & 3) * 2, rq = lane >> 2;

    sB1e[tid] = b1g[tid];
    if (tid < 128) sB2e[tid] = b2g[tid];
#pragma unroll
    for (int c = 0; c < 8; c++)
        cp_async16(sb + E_SW1 + tid * 144 + c * 16, g_ew1 + tid * 128 + c * 16);
#pragma unroll
    for (int c = 0; c < 16; c++)
        cp_async16(sb + E_SW2 + (tid >> 1) * 528 + (tid & 1) * 256 + c * 16,
                   g_ew2 + (tid >> 1) * 512 + (tid & 1) * 256 + c * 16);
#pragma unroll
    for (int c = 0; c < 8; c++)
        cp_async16(sb + E_SX + tid * 144 + c * 16,
                   g_xf16 + (size_t)(row0 + tid) * 128 + c * 16);
    CP_COMMIT();
    CP_WAIT0();
    __syncthreads();

    for (int sbk = 0; sbk < 4; sbk++) {
        if (sbk) __syncthreads();

        float acc1[16][4];
#pragma unroll
        for (int t = 0; t < 16; t++)
#pragma unroll
            for (int q = 0; q < 4; q++) acc1[t][q] = 0.f;
        {
            uint32_t aBase = sb + E_SX + (uint32_t)(sbk * 64 + mt * 16 + (g & 1) * 8 + r8) * 144
                             + (uint32_t)((g >> 1) * 16);
            uint32_t bBase = sb + E_SW1 + (uint32_t)(nh * 128 + (g >> 1) * 8 + r8) * 144
                             + (uint32_t)((g & 1) * 16);
#pragma unroll
            for (int ks = 0; ks < 4; ks++) {
                uint32_t Ah[4];
                ldsm_x4(aBase + ks * 32, Ah[0], Ah[1], Ah[2], Ah[3]);
#pragma unroll
                for (int tp = 0; tp < 8; tp++) {
                    uint32_t Bq[4];
                    ldsm_x4(bBase + tp * 16 * 144 + ks * 32, Bq[0], Bq[1], Bq[2], Bq[3]);
                    mma16816(acc1[tp * 2], Ah, Bq[0], Bq[1]);
                    mma16816(acc1[tp * 2 + 1], Ah, Bq[2], Bq[3]);
                }
            }
        }
#pragma unroll
        for (int nt = 0; nt < 16; nt++) {
            int col = nh * 128 + nt * 8 + cq;
            float b1a = sB1e[col], b1b = sB1e[col + 1];
            int row = mt * 16 + rq;
            __half2 h01 = __floats2half2_rn(fmaxf(acc1[nt][0] + b1a, 0.f),
                                            fmaxf(acc1[nt][1] + b1b, 0.f));
            __half2 h23 = __floats2half2_rn(fmaxf(acc1[nt][2] + b1a, 0.f),
                                            fmaxf(acc1[nt][3] + b1b, 0.f));
            *(__half2*)(smemraw + E_SH + row * 528 + col * 2) = h01;
            *(__half2*)(smemraw + E_SH + (row + 8) * 528 + col * 2) = h23;
        }
        __syncthreads();

        float acc2[8][4];
#pragma unroll
        for (int t = 0; t < 8; t++)
#pragma unroll
            for (int q = 0; q < 4; q++) acc2[t][q] = 0.f;
        {
            uint32_t aBase = sb + E_SH + (uint32_t)(mt * 16 + (g & 1) * 8 + r8) * 528
                             + (uint32_t)((g >> 1) * 16);
            uint32_t bBase = sb + E_SW2 + (uint32_t)(nh * 64 + (g >> 1) * 8 + r8) * 528
                             + (uint32_t)((g & 1) * 16);
#pragma unroll
            for (int ks = 0; ks < 16; ks++) {
                uint32_t Ah[4];
                ldsm_x4(aBase + ks * 32, Ah[0], Ah[1], Ah[2], Ah[3]);
#pragma unroll
                for (int tp = 0; tp < 4; tp++) {
                    uint32_t Bq[4];
                    ldsm_x4(bBase + tp * 16 * 528 + ks * 32, Bq[0], Bq[1], Bq[2], Bq[3]);
                    mma16816(acc2[tp * 2], Ah, Bq[0], Bq[1]);
                    mma16816(acc2[tp * 2 + 1], Ah, Bq[2], Bq[3]);
                }
            }
        }
        __syncthreads();
#pragma unroll
        for (int nt = 0; nt < 8; nt++) {
            int col = nh * 64 + nt * 8 + cq;
            float b2a = sB2e[col], b2b = sB2e[col + 1];
            int row = mt * 16 + rq;
            *(float2*)(smemraw + E_SH + row * 528 + col * 4) =
                make_float2(acc2[nt][0] + b2a, acc2[nt][1] + b2b);
            *(float2*)(smemraw + E_SH + (row + 8) * 528 + col * 4) =
                make_float2(acc2[nt][2] + b2a, acc2[nt][3] + b2b);
        }
        __syncthreads();

        for (int idx = tid; idx < 64 * 64; idx += 256) {
            int r = idx >> 6, c = idx & 63;
            size_t rowAbs = (size_t)row0 + sbk * 64 + r;
            float mu = *(const float*)(smemraw + E_SH + r * 528 + c * 4);
            float lv = *(const float*)(smemraw + E_SH + r * 528 + (64 + c) * 4);
            float e = eps[rowAbs * DD + c];
            float ey = mu + expf(lv * 0.5f) * e;
            outMu[rowAbs * DD + c] = mu;
            outLv[rowAbs * DD + c] = lv;
            *(__half*)(g_abf + rowAbs * 128 + c * 2) = __float2half_rn(ey);
        }
    }
}

// ---------------------------------------------------------------------------
// Decoder v7: paired i (ia, ib=63-ia) per CTA; kmax_a + kmax_b == 5 always.
// grid = (32 pairs, 64 groups of 16 tiles). 1 CTA/SM (reg budget ~190).
// smem: sB1h half2[2][128] @0 (1KB), psum[2][256][8] @2048 (16KB),
//       A0 @18432 (256x144), A1 @55296 (256x144). W_a/W_b staged transiently
//       at A0/A1. Total 92160 B.
// ---------------------------------------------------------------------------
#define RP_A  144
#define DPSUM 2048
#define DA0   18432
#define DA1   55296

static __device__ __forceinline__ void epi_dot(const float acc[8][4], uint32_t b1base,
                                               int nc, const uint32_t w3f[4][2],
                                               float& d0, float& d2) {
    uint32_t h2[16];
#pragma unroll
    for (int nt = 0; nt < 8; nt++) {
        uint32_t b1p;
        asm("ld.shared.b32 %0, [%1];" : "=r"(b1p)
            : "r"(b1base + (uint32_t)(nc * 128 + nt * 16)));
        uint32_t p0, p1;
        asm("cvt.rn.f16x2.f32 %0, %1, %2;" : "=r"(p0) : "f"(acc[nt][1]), "f"(acc[nt][0]));
        asm("cvt.rn.f16x2.f32 %0, %1, %2;" : "=r"(p1) : "f"(acc[nt][3]), "f"(acc[nt][2]));
        asm("add.rn.f16x2 %0, %0, %1;" : "+r"(p0) : "r"(b1p));
        asm("add.rn.f16x2 %0, %0, %1;" : "+r"(p1) : "r"(b1p));
        asm("max.f16x2 %0, %0, %1;" : "+r"(p0) : "r"(0u));
        asm("max.f16x2 %0, %0, %1;" : "+r"(p1) : "r"(0u));
        h2[nt * 2] = p0;
        h2[nt * 2 + 1] = p1;
    }
    float dacc[4] = {0.f, 0.f, 0.f, 0.f};
#pragma unroll
    for (int ks2 = 0; ks2 < 4; ks2++) {
        uint32_t Af[4] = {h2[4 * ks2], h2[4 * ks2 + 1], h2[4 * ks2 + 2], h2[4 * ks2 + 3]};
        mma16816(dacc, Af, w3f[ks2][0], w3f[ks2][1]);
    }
    d0 = dacc[0];
    d2 = dacc[2];
}

__global__ __launch_bounds__(256, 1)
void dec_mma_kernel(const float* __restrict__ b1g,
                    const float* __restrict__ w3g,
                    const float* __restrict__ b3g,
                    float* __restrict__ outX,
                    float* __restrict__ outYr) {
    uint32_t sb = smem_u32(smemraw);
    __half2* sB1h = (__half2*)smemraw;            // [2][128]
    float* psum = (float*)(smemraw + DPSUM);      // [2][256][8]
    int tid = threadIdx.x, wid = tid >> 5, lane = tid & 31;
    int ia = blockIdx.x, ib = 63 - ia;
    int tile0 = blockIdx.y * 16;
    int nc = wid & 3, rh = wid >> 2;
    const int ka = (ia >> 4) + 1;                 // 1..2
    const int kb = (ib >> 4) + 1;                 // 3..4 (ka+kb == 5)
    const int kc2m = 2 * kb;                      // A chunks to stage (kb = max)

    // ---- stage W_a @A0, W_b @A1, packed b1 for both ----
    {
        const unsigned char* wa = g_wbf + (size_t)ia * 32768;
        const unsigned char* wb = g_wbf + (size_t)ib * 32768;
#pragma unroll
        for (int c = 0; c < 4; c++)
            if (c < 2 * ka)
                cp_async16(sb + DA0 + tid * RP_A + c * 16, wa + tid * 128 + c * 16);
#pragma unroll
        for (int c = 0; c < 8; c++)
            if (c < 2 * kb)
                cp_async16(sb + DA1 + tid * RP_A + c * 16, wb + tid * 128 + c * 16);
        CP_COMMIT();
        if (tid < 128) {
            sB1h[tid] = __floats2half2_rn(b1g[ia * HID + 2 * tid], b1g[ia * HID + 2 * tid + 1]);
            sB1h[128 + tid] = __floats2half2_rn(b1g[ib * HID + 2 * tid], b1g[ib * HID + 2 * tid + 1]);
        }
    }
    float b3a = b3g[ia], b3b = b3g[ib];

    // ---- w3 B-fragments for both i (col 0 = w3, cols 1..7 = 0) ----
    uint32_t w3fa[4][2], w3fb[4][2];
#pragma unroll
    for (int q = 0; q < 4; q++) { w3fa[q][0] = w3fa[q][1] = 0u; w3fb[q][0] = w3fb[q][1] = 0u; }
    if ((lane >> 2) == 0) {
#pragma unroll
        for (int ks2 = 0; ks2 < 4; ks2++) {
            int k0 = nc * 64 + ks2 * 16 + (lane & 3) * 2;
            __half2 lo = __floats2half2_rn(w3g[ia * HID + k0], w3g[ia * HID + k0 + 1]);
            __half2 hi = __floats2half2_rn(w3g[ia * HID + k0 + 8], w3g[ia * HID + k0 + 9]);
            w3fa[ks2][0] = *(uint32_t*)&lo;
            w3fa[ks2][1] = *(uint32_t*)&hi;
            __half2 lo2 = __floats2half2_rn(w3g[ib * HID + k0], w3g[ib * HID + k0 + 1]);
            __half2 hi2 = __floats2half2_rn(w3g[ib * HID + k0 + 8], w3g[ib * HID + k0 + 9]);
            w3fb[ks2][0] = *(uint32_t*)&lo2;
            w3fb[ks2][1] = *(uint32_t*)&hi2;
        }
    }
    CP_WAIT0();
    __syncthreads();

    // ---- load both warps' main-GEMM B fragments into registers ----
    int r8 = lane & 7, g = lane >> 3;
    uint32_t Bha[2][16], Bhb[4][16];
#pragma unroll
    for (int ks = 0; ks < 2; ks++)
#pragma unroll
        for (int q = 0; q < 16; q++) Bha[ks][q] = 0u;
#pragma unroll
    for (int ks = 0; ks < 4; ks++)
#pragma unroll
        for (int q = 0; q < 16; q++) Bhb[ks][q] = 0u;
    {
        uint32_t bRow = (uint32_t)((g >> 1) * 8 + r8);
        uint32_t bCol = (uint32_t)((g & 1) * 16);
        uint32_t bOff = (uint32_t)(nc * 64 + bRow) * RP_A + bCol;
#pragma unroll
        for (int ks = 0; ks < 2; ks++)
            if (ks < ka) {
#pragma unroll
                for (int tp = 0; tp < 4; tp++) {
                    uint32_t a = sb + DA0 + bOff + tp * 16 * RP_A + ks * 32;
                    ldsm_x4(a, Bha[ks][tp * 4], Bha[ks][tp * 4 + 1],
                            Bha[ks][tp * 4 + 2], Bha[ks][tp * 4 + 3]);
                }
            }
#pragma unroll
        for (int ks = 0; ks < 4; ks++)
            if (ks < kb) {
#pragma unroll
                for (int tp = 0; tp < 4; tp++) {
                    uint32_t a = sb + DA1 + bOff + tp * 16 * RP_A + ks * 32;
                    ldsm_x4(a, Bhb[ks][tp * 4], Bhb[ks][tp * 4 + 1],
                            Bhb[ks][tp * 4 + 2], Bhb[ks][tp * 4 + 3]);
                }
            }
    }
    __syncthreads();   // W regions free; A buffers may reuse them

    // ---- prefetch A tile 0 (kc2m chunks) ----
    {
        const unsigned char* src = g_abf + (size_t)tile0 * 256 * 128;
#pragma unroll
        for (int c = 0; c < 8; c++)
            if (c < kc2m)
                cp_async16(sb + DA0 + tid * RP_A + c * 16, src + tid * 128 + c * 16);
        CP_COMMIT();
    }

    uint32_t aRowBase = (uint32_t)(rh * 128 + (g & 1) * 8 + r8);
    uint32_t aCol = (uint32_t)((g >> 1) * 16);
    int rq = lane >> 2;
    uint32_t b1aAddr = sb + (uint32_t)((lane & 3) * 4);        // i_a half2 table
    uint32_t b1bAddr = b1aAddr + 512u;                         // i_b half2 table

    for (int j = 0; j < 16; j++) {
        CP_WAIT0();
        __syncthreads();
        int buf = j & 1;
        if (j + 1 < 16) {
            const unsigned char* src = g_abf + (size_t)(tile0 + j + 1) * 256 * 128;
            uint32_t dstOff = buf ? DA0 : DA1;
#pragma unroll
            for (int c = 0; c < 8; c++)
                if (c < kc2m)
                    cp_async16(sb + dstOff + tid * RP_A + c * 16, src + tid * 128 + c * 16);
            CP_COMMIT();
        }

        uint32_t aTile = sb + (buf ? DA1 : DA0);
#pragma unroll 1
        for (int mb = 0; mb < 8; mb++) {
            uint32_t aBase = aTile + (aRowBase + mb * 16) * RP_A + aCol;
            int row = rh * 128 + mb * 16 + rq;

            // ---- i_a ----
            {
                float acc[8][4];
#pragma unroll
                for (int t = 0; t < 8; t++)
#pragma unroll
                    for (int q = 0; q < 4; q++) acc[t][q] = 0.f;
#pragma unroll
                for (int ks = 0; ks < 2; ks++) {
                    if (ks < ka) {
                        uint32_t Ah[4];
                        ldsm_x4(aBase + ks * 32, Ah[0], Ah[1], Ah[2], Ah[3]);
#pragma unroll
                        for (int nt = 0; nt < 8; nt++)
                            mma16816(acc[nt], Ah, Bha[ks][nt * 2], Bha[ks][nt * 2 + 1]);
                    }
                }
                float d0, d2;
                epi_dot(acc, b1aAddr, nc, w3fa, d0, d2);
                if ((lane & 3) == 0) {
                    psum[buf * 2048 + row * 8 + nc] = d0;
                    psum[buf * 2048 + (row + 8) * 8 + nc] = d2;
                }
            }
            // ---- i_b ----
            {
                float acc[8][4];
#pragma unroll
                for (int t = 0; t < 8; t++)
#pragma unroll
                    for (int q = 0; q < 4; q++) acc[t][q] = 0.f;
#pragma unroll
                for (int ks = 0; ks < 4; ks++) {
                    if (ks < kb) {
                        uint32_t Ah[4];
                        ldsm_x4(aBase + ks * 32, Ah[0], Ah[1], Ah[2], Ah[3]);
#pragma unroll
                        for (int nt = 0; nt < 8; nt++)
                            mma16816(acc[nt], Ah, Bhb[ks][nt * 2], Bhb[ks][nt * 2 + 1]);
                    }
                }
                float d0, d2;
                epi_dot(acc, b1bAddr, nc, w3fb, d0, d2);
                if ((lane & 3) == 0) {
                    psum[buf * 2048 + row * 8 + 4 + nc] = d0;
                    psum[buf * 2048 + (row + 8) * 8 + 4 + nc] = d2;
                }
            }
        }
        __syncthreads();
        {
            const float* p = &psum[buf * 2048 + tid * 8];
            float oa = p[0] + p[1] + p[2] + p[3] + b3a;
            float ob = p[4] + p[5] + p[6] + p[7] + b3b;
            size_t grow = (size_t)(tile0 + j) * 256 + tid;
            outX[grow * 64 + ia] = oa;
            outX[grow * 64 + ib] = ob;
            outYr[grow * 128 + ia] = oa;
            outYr[grow * 128 + ib] = ob;
            outYr[grow * 128 + 64 + ia] = 0.f;
            outYr[grow * 128 + 64 + ib] = 0.f;
        }
    }
}

// ---------------------------------------------------------------------------
extern "C" void kernel_launch(void* const* d_in, const int* in_sizes, int n_in,
                              void* d_out, int out_size) {
    const float* x      = (const float*)d_in[0];
    const float* eps    = (const float*)d_in[1];
    const float* enc1_w = (const float*)d_in[2];
    const float* enc1_b = (const float*)d_in[3];
    const float* enc3_w = (const float*)d_in[4];
    const float* enc3_b = (const float*)d_in[5];
    const float* dec1_w = (const float*)d_in[6];
    const float* dec1_b = (const float*)d_in[7];
    const float* dec3_w = (const float*)d_in[8];
    const float* dec3_b = (const float*)d_in[9];
    const unsigned char* bmask = (const unsigned char*)d_in[10];
    (void)n_in; (void)in_sizes; (void)out_size;

    float* out   = (float*)d_out;
    float* outX  = out;
    float* outMu = out + (size_t)BATCH * DD;
    float* outLv = out + (size_t)2 * BATCH * DD;
    float* outYr = out + (size_t)3 * BATCH * DD;

    size_t sEnc = 176640;
    size_t sDec = 92160;
    cudaFuncSetAttribute(enc_mma_kernel, cudaFuncAttributeMaxDynamicSharedMemorySize, (int)sEnc);
    cudaFuncSetAttribute(dec_mma_kernel, cudaFuncAttributeMaxDynamicSharedMemorySize, (int)sDec);

    mask_expand_kernel<<<1, 256>>>(bmask);
    wprep_kernel<<<DD, 256>>>(dec1_w);
    ewprep_kernel<<<32, 256>>>(enc1_w, enc3_w);
    xprep_kernel<<<(BATCH * 32) / 256, 256>>>((const float2*)x);
    enc_mma_kernel<<<BATCH / 256, 256, sEnc>>>(eps, enc1_b, enc3_b, outMu, outLv);
    dec_mma_kernel<<<dim3(32, NT256 / 16), 256, sDec>>>(dec1_b, dec3_w, dec3_b, outX, outYr);
}

// round 16
// speedup vs baseline: 1.0639x; 1.0639x over previous
#include <cuda_runtime.h>
#include <cuda_fp16.h>
#include <cstdint>

// ---------------------------------------------------------------------------
// CausalVAE2: B=262144, D=64, HID=256
// out layout: [x_out B*64][mu B*64][log_var B*64][y_recon B*128]
// Encoder + decoder on mma.sync fp16 (1-term). Decoder = R14 structure
// (unpaired, 2 CTAs/SM) with ks2-streamed epilogue to fit 128 regs (no
// spills). xprep folded into encoder staging.
// ---------------------------------------------------------------------------

#define BATCH 262144
#define DD 64
#define HID 256
#define NT256 (BATCH / 256)           // 1024 row tiles of 256

// Scratch (device globals)
__device__ __align__(16) unsigned char g_abf[(size_t)BATCH * 128];  // 32MB eps_y fp16 [row][64k]
__device__ __align__(16) unsigned char g_wbf[(size_t)DD * 32768];   // 2MB dec W' [n][k] fp16
__device__ __align__(16) unsigned char g_ew1[256 * 128];            // enc W1 B-layout fp16
__device__ __align__(16) unsigned char g_ew2[128 * 512];            // enc W2 B-layout fp16
__device__ int g_mask[DD * DD];

// ---- baseline tensor-core primitives --------------------------------------
static __device__ __forceinline__ uint32_t smem_u32(const void* p) {
    uint32_t a;
    asm("{ .reg .u64 t; cvta.to.shared.u64 t, %1; cvt.u32.u64 %0, t; }" : "=r"(a) : "l"(p));
    return a;
}
static __device__ __forceinline__ void ldsm_x4(uint32_t addr, uint32_t& r0, uint32_t& r1,
                                               uint32_t& r2, uint32_t& r3) {
    asm volatile("ldmatrix.sync.aligned.m8n8.x4.shared.b16 {%0,%1,%2,%3}, [%4];"
                 : "=r"(r0), "=r"(r1), "=r"(r2), "=r"(r3) : "r"(addr));
}
static __device__ __forceinline__ void mma16816(float* d, const uint32_t* a,
                                                uint32_t b0, uint32_t b1) {
    asm volatile("mma.sync.aligned.m16n8k16.row.col.f32.f16.f16.f32 "
                 "{%0,%1,%2,%3}, {%4,%5,%6,%7}, {%8,%9}, {%0,%1,%2,%3};"
                 : "+f"(d[0]), "+f"(d[1]), "+f"(d[2]), "+f"(d[3])
                 : "r"(a[0]), "r"(a[1]), "r"(a[2]), "r"(a[3]), "r"(b0), "r"(b1));
}
static __device__ __forceinline__ void cp_async16(uint32_t dst, const void* src) {
    asm volatile("cp.async.cg.shared.global [%0], [%1], 16;" :: "r"(dst), "l"(src));
}
#define CP_COMMIT() asm volatile("cp.async.commit_group;" ::: "memory")
#define CP_WAIT0()  asm volatile("cp.async.wait_group 0;" ::: "memory")

extern __shared__ __align__(1024) char smemraw[];

// ---------------------------------------------------------------------------
// Mask decode (robust to bool delivered as u8 / i32 / f32)
// ---------------------------------------------------------------------------
__global__ void mask_expand_kernel(const unsigned char* __restrict__ mb) {
    __shared__ int flags[2];
    __shared__ int s_mode;
    int tid = threadIdx.x;
    if (tid < 2) flags[tid] = 0;
    __syncthreads();
    for (int idx = tid; idx < DD * DD; idx += blockDim.x) {
        unsigned char b = mb[idx];
        if ((idx & 3) != 0 && b != 0) {
            atomicOr(&flags[1], 1);
            if (b > 1) atomicOr(&flags[0], 1);
        }
    }
    __syncthreads();
    if (tid == 0) s_mode = flags[0] ? 2 : (flags[1] ? 1 : 0);
    __syncthreads();
    int mode = s_mode;
    for (int idx = tid; idx < DD * DD; idx += blockDim.x) {
        int v;
        if (mode == 2)      v = (((const float*)mb)[idx] != 0.0f);
        else if (mode == 1) v = (mb[idx] != 0);
        else                v = (((const int*)mb)[idx] != 0);
        g_mask[idx] = v;
    }
}

// ---------------------------------------------------------------------------
// Decoder W-prep: masked dec1_w -> fp16, layout [n][k].
// ---------------------------------------------------------------------------
__global__ void wprep_kernel(const float* __restrict__ w1g) {
    int i = blockIdx.x, tid = threadIdx.x;
    unsigned char* wb = g_wbf + (size_t)i * 32768;
    for (int idx = tid; idx < DD * HID; idx += blockDim.x) {
        int k = idx >> 8, n = idx & 255;
        float m = (float)g_mask[k * DD + i];
        float w = w1g[(size_t)i * DD * HID + (size_t)k * HID + n] * m;
        *(__half*)(wb + n * 128 + k * 2) = __float2half_rn(w);
    }
}

// ---------------------------------------------------------------------------
// Encoder W-prep: enc1_w -> [n][k]; enc3_w -> [n][k]. fp16.
// ---------------------------------------------------------------------------
__global__ void ewprep_kernel(const float* __restrict__ w1,
                              const float* __restrict__ w2) {
    int t = blockIdx.x * 256 + threadIdx.x;
    int stride = gridDim.x * 256;
    for (int idx = t; idx < 64 * 256; idx += stride) {
        int n = idx >> 6, k = idx & 63;
        *(__half*)(g_ew1 + n * 128 + k * 2) = __float2half_rn(w1[k * 256 + n]);
    }
    for (int idx = t; idx < 256 * 128; idx += stride) {
        int n = idx >> 8, k = idx & 255;
        *(__half*)(g_ew2 + n * 512 + k * 2) = __float2half_rn(w2[k * 128 + n]);
    }
}

// ---------------------------------------------------------------------------
// Tensor-core fused encoder (R13 structure; x staged directly from fp32).
// ---------------------------------------------------------------------------
#define E_SB1 0
#define E_SB2 1024
#define E_SW1 1536
#define E_SW2 38400
#define E_SX  105984
#define E_SH  142848

__global__ __launch_bounds__(256, 1)
void enc_mma_kernel(const float* __restrict__ x,
                    const float* __restrict__ eps,
                    const float* __restrict__ b1g,
                    const float* __restrict__ b2g,
                    float* __restrict__ outMu,
                    float* __restrict__ outLv) {
    uint32_t sb = smem_u32(smemraw);
    float* sB1e = (float*)(smemraw + E_SB1);
    float* sB2e = (float*)(smemraw + E_SB2);
    int tid = threadIdx.x, wid = tid >> 5, lane = tid & 31;
    int row0 = blockIdx.x * 256;
    int r8 = lane & 7, g = lane >> 3;
    int mt = wid & 3, nh = wid >> 2;
    int cq = (lane & 3) * 2, rq = lane >> 2;

    sB1e[tid] = b1g[tid];
    if (tid < 128) sB2e[tid] = b2g[tid];
#pragma unroll
    for (int c = 0; c < 8; c++)
        cp_async16(sb + E_SW1 + tid * 144 + c * 16, g_ew1 + tid * 128 + c * 16);
#pragma unroll
    for (int c = 0; c < 16; c++)
        cp_async16(sb + E_SW2 + (tid >> 1) * 528 + (tid & 1) * 256 + c * 16,
                   g_ew2 + (tid >> 1) * 512 + (tid & 1) * 256 + c * 16);
    CP_COMMIT();
    // stage x fp32 -> fp16 directly (xprep folded in)
    {
        const float4* xr = (const float4*)(x + (size_t)(row0 + tid) * 64);
#pragma unroll
        for (int c = 0; c < 16; c++) {
            float4 v = xr[c];
            __half2 a = __floats2half2_rn(v.x, v.y);
            __half2 b = __floats2half2_rn(v.z, v.w);
            *(uint32_t*)(smemraw + E_SX + tid * 144 + c * 8)     = *(uint32_t*)&a;
            *(uint32_t*)(smemraw + E_SX + tid * 144 + c * 8 + 4) = *(uint32_t*)&b;
        }
    }
    CP_WAIT0();
    __syncthreads();

    for (int sbk = 0; sbk < 4; sbk++) {
        if (sbk) __syncthreads();

        float acc1[16][4];
#pragma unroll
        for (int t = 0; t < 16; t++)
#pragma unroll
            for (int q = 0; q < 4; q++) acc1[t][q] = 0.f;
        {
            uint32_t aBase = sb + E_SX + (uint32_t)(sbk * 64 + mt * 16 + (g & 1) * 8 + r8) * 144
                             + (uint32_t)((g >> 1) * 16);
            uint32_t bBase = sb + E_SW1 + (uint32_t)(nh * 128 + (g >> 1) * 8 + r8) * 144
                             + (uint32_t)((g & 1) * 16);
#pragma unroll
            for (int ks = 0; ks < 4; ks++) {
                uint32_t Ah[4];
                ldsm_x4(aBase + ks * 32, Ah[0], Ah[1], Ah[2], Ah[3]);
#pragma unroll
                for (int tp = 0; tp < 8; tp++) {
                    uint32_t Bq[4];
                    ldsm_x4(bBase + tp * 16 * 144 + ks * 32, Bq[0], Bq[1], Bq[2], Bq[3]);
                    mma16816(acc1[tp * 2], Ah, Bq[0], Bq[1]);
                    mma16816(acc1[tp * 2 + 1], Ah, Bq[2], Bq[3]);
                }
            }
        }
#pragma unroll
        for (int nt = 0; nt < 16; nt++) {
            int col = nh * 128 + nt * 8 + cq;
            float b1a = sB1e[col], b1b = sB1e[col + 1];
            int row = mt * 16 + rq;
            __half2 h01 = __floats2half2_rn(fmaxf(acc1[nt][0] + b1a, 0.f),
                                            fmaxf(acc1[nt][1] + b1b, 0.f));
            __half2 h23 = __floats2half2_rn(fmaxf(acc1[nt][2] + b1a, 0.f),
                                            fmaxf(acc1[nt][3] + b1b, 0.f));
            *(__half2*)(smemraw + E_SH + row * 528 + col * 2) = h01;
            *(__half2*)(smemraw + E_SH + (row + 8) * 528 + col * 2) = h23;
        }
        __syncthreads();

        float acc2[8][4];
#pragma unroll
        for (int t = 0; t < 8; t++)
#pragma unroll
            for (int q = 0; q < 4; q++) acc2[t][q] = 0.f;
        {
            uint32_t aBase = sb + E_SH + (uint32_t)(mt * 16 + (g & 1) * 8 + r8) * 528
                             + (uint32_t)((g >> 1) * 16);
            uint32_t bBase = sb + E_SW2 + (uint32_t)(nh * 64 + (g >> 1) * 8 + r8) * 528
                             + (uint32_t)((g & 1) * 16);
#pragma unroll
            for (int ks = 0; ks < 16; ks++) {
                uint32_t Ah[4];
                ldsm_x4(aBase + ks * 32, Ah[0], Ah[1], Ah[2], Ah[3]);
#pragma unroll
                for (int tp = 0; tp < 4; tp++) {
                    uint32_t Bq[4];
                    ldsm_x4(bBase + tp * 16 * 528 + ks * 32, Bq[0], Bq[1], Bq[2], Bq[3]);
                    mma16816(acc2[tp * 2], Ah, Bq[0], Bq[1]);
                    mma16816(acc2[tp * 2 + 1], Ah, Bq[2], Bq[3]);
                }
            }
        }
        __syncthreads();
#pragma unroll
        for (int nt = 0; nt < 8; nt++) {
            int col = nh * 64 + nt * 8 + cq;
            float b2a = sB2e[col], b2b = sB2e[col + 1];
            int row = mt * 16 + rq;
            *(float2*)(smemraw + E_SH + row * 528 + col * 4) =
                make_float2(acc2[nt][0] + b2a, acc2[nt][1] + b2b);
            *(float2*)(smemraw + E_SH + (row + 8) * 528 + col * 4) =
                make_float2(acc2[nt][2] + b2a, acc2[nt][3] + b2b);
        }
        __syncthreads();

        for (int idx = tid; idx < 64 * 64; idx += 256) {
            int r = idx >> 6, c = idx & 63;
            size_t rowAbs = (size_t)row0 + sbk * 64 + r;
            float mu = *(const float*)(smemraw + E_SH + r * 528 + c * 4);
            float lv = *(const float*)(smemraw + E_SH + r * 528 + (64 + c) * 4);
            float e = eps[rowAbs * DD + c];
            float ey = mu + expf(lv * 0.5f) * e;
            outMu[rowAbs * DD + c] = mu;
            outLv[rowAbs * DD + c] = lv;
            *(__half*)(g_abf + rowAbs * 128 + c * 2) = __float2half_rn(ey);
        }
    }
}

// ---------------------------------------------------------------------------
// Decoder v8 = R14 structure (unpaired, 2 CTAs/SM) with ks2-streamed epilogue
// (no h2[16] buffer -> fits 128 regs without spills).
// smem: sB1h half2[128] @0, psum[2][256][4] @2048, A0 @10240 (256x144),
//       A1 @47104; W' staged transiently at A0. Total 83968 B.
// ---------------------------------------------------------------------------
#define RP_A  144
#define SW_OFF  10240
#define SA0_OFF 10240
#define SA1_OFF 47104
#define PSUM_OFF 2048

__global__ __launch_bounds__(256, 2)
void dec_mma_kernel(const float* __restrict__ b1g,
                    const float* __restrict__ w3g,
                    const float* __restrict__ b3g,
                    float* __restrict__ outX,
                    float* __restrict__ outYr) {
    uint32_t sb = smem_u32(smemraw);
    __half2* sB1h = (__half2*)smemraw;            // 128 half2
    float* psum = (float*)(smemraw + PSUM_OFF);   // [2][256][4]
    int tid = threadIdx.x, wid = tid >> 5, lane = tid & 31;
    int i = blockIdx.x;
    int tile0 = blockIdx.y * 16;
    int nc = wid & 3, rh = wid >> 2;
    const int kmax = (i >> 4) + 1;
    const int kc2 = 2 * kmax;

    // ---- stage W' fp16 + packed b1 ----
    {
        const unsigned char* src = g_wbf + (size_t)i * 32768;
#pragma unroll
        for (int c = 0; c < 8; c++)
            if (c < kc2)
                cp_async16(sb + SW_OFF + tid * RP_A + c * 16, src + tid * 128 + c * 16);
        CP_COMMIT();
        if (tid < 128)
            sB1h[tid] = __floats2half2_rn(b1g[i * HID + 2 * tid], b1g[i * HID + 2 * tid + 1]);
    }
    float b3v = b3g[i];

    // ---- build this warp's w3 B-fragments (col 0 = w3, cols 1..7 = 0) ----
    uint32_t w3f[4][2];
#pragma unroll
    for (int ks2 = 0; ks2 < 4; ks2++) { w3f[ks2][0] = 0u; w3f[ks2][1] = 0u; }
    if ((lane >> 2) == 0) {
#pragma unroll
        for (int ks2 = 0; ks2 < 4; ks2++) {
            int k0 = nc * 64 + ks2 * 16 + (lane & 3) * 2;
            __half2 lo = __floats2half2_rn(w3g[i * HID + k0], w3g[i * HID + k0 + 1]);
            __half2 hi = __floats2half2_rn(w3g[i * HID + k0 + 8], w3g[i * HID + k0 + 9]);
            w3f[ks2][0] = *(uint32_t*)&lo;
            w3f[ks2][1] = *(uint32_t*)&hi;
        }
    }
    CP_WAIT0();
    __syncthreads();

    // ---- load this warp's main-GEMM B fragments into registers ----
    int r8 = lane & 7, g = lane >> 3;
    uint32_t Bh[4][16];
#pragma unroll
    for (int ks = 0; ks < 4; ks++)
#pragma unroll
        for (int q = 0; q < 16; q++) Bh[ks][q] = 0u;
    {
        uint32_t bRow = (uint32_t)((g >> 1) * 8 + r8);
        uint32_t bCol = (uint32_t)((g & 1) * 16);
        uint32_t bBase = sb + SW_OFF + (uint32_t)(nc * 64 + bRow) * RP_A + bCol;
#pragma unroll
        for (int ks = 0; ks < 4; ks++) {
            if (ks < kmax) {
#pragma unroll
                for (int tp = 0; tp < 4; tp++) {
                    uint32_t a = bBase + tp * 16 * RP_A + ks * 32;
                    ldsm_x4(a, Bh[ks][tp * 4], Bh[ks][tp * 4 + 1],
                            Bh[ks][tp * 4 + 2], Bh[ks][tp * 4 + 3]);
                }
            }
        }
    }
    __syncthreads();   // W' region free; A buffers may reuse it

    // ---- prefetch A tile 0 ----
    {
        const unsigned char* src = g_abf + (size_t)tile0 * 256 * 128;
#pragma unroll
        for (int c = 0; c < 8; c++)
            if (c < kc2)
                cp_async16(sb + SA0_OFF + tid * RP_A + c * 16, src + tid * 128 + c * 16);
        CP_COMMIT();
    }

    uint32_t aRowBase = (uint32_t)(rh * 128 + (g & 1) * 8 + r8);
    uint32_t aCol = (uint32_t)((g >> 1) * 16);
    int rq = lane >> 2;
    uint32_t b1addr = sb + (uint32_t)((lane & 3) * 4) + (uint32_t)(nc * 128);

    for (int j = 0; j < 16; j++) {
        CP_WAIT0();
        __syncthreads();
        int buf = j & 1;
        if (j + 1 < 16) {
            const unsigned char* src = g_abf + (size_t)(tile0 + j + 1) * 256 * 128;
            uint32_t dstOff = buf ? SA0_OFF : SA1_OFF;
#pragma unroll
            for (int c = 0; c < 8; c++)
                if (c < kc2)
                    cp_async16(sb + dstOff + tid * RP_A + c * 16, src + tid * 128 + c * 16);
            CP_COMMIT();
        }

        uint32_t aTile = sb + (buf ? SA1_OFF : SA0_OFF);
#pragma unroll 1
        for (int mb = 0; mb < 8; mb++) {
            uint32_t aBase = aTile + (aRowBase + mb * 16) * RP_A + aCol;
            float acc[8][4];
#pragma unroll
            for (int t = 0; t < 8; t++)
#pragma unroll
                for (int q = 0; q < 4; q++) acc[t][q] = 0.f;

#pragma unroll
            for (int ks = 0; ks < 4; ks++) {
                if (ks < kmax) {
                    uint32_t Ah[4];
                    ldsm_x4(aBase + ks * 32, Ah[0], Ah[1], Ah[2], Ah[3]);
#pragma unroll
                    for (int nt = 0; nt < 8; nt++)
                        mma16816(acc[nt], Ah, Bh[ks][nt * 2], Bh[ks][nt * 2 + 1]);
                }
            }

            // ---- ks2-streamed epilogue: relu(acc+b1) fp16 -> dot(w3) MMAs,
            // no h2 buffer (only Af[4] live) ----
            float dacc[4] = {0.f, 0.f, 0.f, 0.f};
#pragma unroll
            for (int ks2 = 0; ks2 < 4; ks2++) {
                uint32_t Af[4];
#pragma unroll
                for (int h = 0; h < 2; h++) {
                    int nt = 2 * ks2 + h;
                    uint32_t b1p;
                    asm("ld.shared.b32 %0, [%1];" : "=r"(b1p)
                        : "r"(b1addr + (uint32_t)(nt * 16)));
                    uint32_t p0, p1;
                    asm("cvt.rn.f16x2.f32 %0, %1, %2;" : "=r"(p0)
                        : "f"(acc[nt][1]), "f"(acc[nt][0]));
                    asm("cvt.rn.f16x2.f32 %0, %1, %2;" : "=r"(p1)
                        : "f"(acc[nt][3]), "f"(acc[nt][2]));
                    asm("add.rn.f16x2 %0, %0, %1;" : "+r"(p0) : "r"(b1p));
                    asm("add.rn.f16x2 %0, %0, %1;" : "+r"(p1) : "r"(b1p));
                    asm("max.f16x2 %0, %0, %1;" : "+r"(p0) : "r"(0u));
                    asm("max.f16x2 %0, %0, %1;" : "+r"(p1) : "r"(0u));
                    Af[2 * h] = p0;
                    Af[2 * h + 1] = p1;
                }
                mma16816(dacc, Af, w3f[ks2][0], w3f[ks2][1]);
            }
            if ((lane & 3) == 0) {
                int row = rh * 128 + mb * 16 + rq;
                psum[buf * 1024 + row * 4 + nc] = dacc[0];
                psum[buf * 1024 + (row + 8) * 4 + nc] = dacc[2];
            }
        }
        __syncthreads();
        {
            float o = psum[buf * 1024 + tid * 4 + 0] + psum[buf * 1024 + tid * 4 + 1] +
                      psum[buf * 1024 + tid * 4 + 2] + psum[buf * 1024 + tid * 4 + 3] + b3v;
            size_t grow = (size_t)(tile0 + j) * 256 + tid;
            outX[grow * 64 + i] = o;
            outYr[grow * 128 + i] = o;
            outYr[grow * 128 + 64 + i] = 0.f;   // zero half folded in
        }
    }
}

// ---------------------------------------------------------------------------
extern "C" void kernel_launch(void* const* d_in, const int* in_sizes, int n_in,
                              void* d_out, int out_size) {
    const float* x      = (const float*)d_in[0];
    const float* eps    = (const float*)d_in[1];
    const float* enc1_w = (const float*)d_in[2];
    const float* enc1_b = (const float*)d_in[3];
    const float* enc3_w = (const float*)d_in[4];
    const float* enc3_b = (const float*)d_in[5];
    const float* dec1_w = (const float*)d_in[6];
    const float* dec1_b = (const float*)d_in[7];
    const float* dec3_w = (const float*)d_in[8];
    const float* dec3_b = (const float*)d_in[9];
    const unsigned char* bmask = (const unsigned char*)d_in[10];
    (void)n_in; (void)in_sizes; (void)out_size;

    float* out   = (float*)d_out;
    float* outX  = out;
    float* outMu = out + (size_t)BATCH * DD;
    float* outLv = out + (size_t)2 * BATCH * DD;
    float* outYr = out + (size_t)3 * BATCH * DD;

    size_t sEnc = 176640;
    size_t sDec = 83968;
    cudaFuncSetAttribute(enc_mma_kernel, cudaFuncAttributeMaxDynamicSharedMemorySize, (int)sEnc);
    cudaFuncSetAttribute(dec_mma_kernel, cudaFuncAttributeMaxDynamicSharedMemorySize, (int)sDec);

    mask_expand_kernel<<<1, 256>>>(bmask);
    wprep_kernel<<<DD, 256>>>(dec1_w);
    ewprep_kernel<<<32, 256>>>(enc1_w, enc3_w);
    enc_mma_kernel<<<BATCH / 256, 256, sEnc>>>(x, eps, enc1_b, enc3_b, outMu, outLv);
    dec_mma_kernel<<<dim3(DD, NT256 / 16), 256, sDec>>>(dec1_b, dec3_w, dec3_b, outX, outYr);
}

// round 17
// speedup vs baseline: 1.2324x; 1.1584x over previous
#include <cuda_runtime.h>
#include <cuda_fp16.h>
#include <cstdint>

// ---------------------------------------------------------------------------
// CausalVAE2: B=262144, D=64, HID=256
// out layout: [x_out B*64][mu B*64][log_var B*64][y_recon B*128]
// Encoder + decoder on mma.sync fp16 (1-term). Decoder: R16 structure with
// (a) split epilogue dacc chains, (b) coalesced transposed output staging
// (g_gout[i][row]) + separate coalesced transpose kernel.
// ---------------------------------------------------------------------------

#define BATCH 262144
#define DD 64
#define HID 256
#define NT256 (BATCH / 256)           // 1024 row tiles of 256

// Scratch (device globals)
__device__ __align__(16) unsigned char g_abf[(size_t)BATCH * 128];  // 32MB eps_y fp16 [row][64k]
__device__ __align__(16) unsigned char g_wbf[(size_t)DD * 32768];   // 2MB dec W' [n][k] fp16
__device__ __align__(16) unsigned char g_ew1[256 * 128];            // enc W1 B-layout fp16
__device__ __align__(16) unsigned char g_ew2[128 * 512];            // enc W2 B-layout fp16
__device__ __align__(16) float g_gout[(size_t)DD * BATCH];          // 64MB decoder out [i][row]
__device__ int g_mask[DD * DD];

// ---- baseline tensor-core primitives --------------------------------------
static __device__ __forceinline__ uint32_t smem_u32(const void* p) {
    uint32_t a;
    asm("{ .reg .u64 t; cvta.to.shared.u64 t, %1; cvt.u32.u64 %0, t; }" : "=r"(a) : "l"(p));
    return a;
}
static __device__ __forceinline__ void ldsm_x4(uint32_t addr, uint32_t& r0, uint32_t& r1,
                                               uint32_t& r2, uint32_t& r3) {
    asm volatile("ldmatrix.sync.aligned.m8n8.x4.shared.b16 {%0,%1,%2,%3}, [%4];"
                 : "=r"(r0), "=r"(r1), "=r"(r2), "=r"(r3) : "r"(addr));
}
static __device__ __forceinline__ void mma16816(float* d, const uint32_t* a,
                                                uint32_t b0, uint32_t b1) {
    asm volatile("mma.sync.aligned.m16n8k16.row.col.f32.f16.f16.f32 "
                 "{%0,%1,%2,%3}, {%4,%5,%6,%7}, {%8,%9}, {%0,%1,%2,%3};"
                 : "+f"(d[0]), "+f"(d[1]), "+f"(d[2]), "+f"(d[3])
                 : "r"(a[0]), "r"(a[1]), "r"(a[2]), "r"(a[3]), "r"(b0), "r"(b1));
}
static __device__ __forceinline__ void cp_async16(uint32_t dst, const void* src) {
    asm volatile("cp.async.cg.shared.global [%0], [%1], 16;" :: "r"(dst), "l"(src));
}
#define CP_COMMIT() asm volatile("cp.async.commit_group;" ::: "memory")
#define CP_WAIT0()  asm volatile("cp.async.wait_group 0;" ::: "memory")

extern __shared__ __align__(1024) char smemraw[];

// ---------------------------------------------------------------------------
// Mask decode (robust to bool delivered as u8 / i32 / f32)
// ---------------------------------------------------------------------------
__global__ void mask_expand_kernel(const unsigned char* __restrict__ mb) {
    __shared__ int flags[2];
    __shared__ int s_mode;
    int tid = threadIdx.x;
    if (tid < 2) flags[tid] = 0;
    __syncthreads();
    for (int idx = tid; idx < DD * DD; idx += blockDim.x) {
        unsigned char b = mb[idx];
        if ((idx & 3) != 0 && b != 0) {
            atomicOr(&flags[1], 1);
            if (b > 1) atomicOr(&flags[0], 1);
        }
    }
    __syncthreads();
    if (tid == 0) s_mode = flags[0] ? 2 : (flags[1] ? 1 : 0);
    __syncthreads();
    int mode = s_mode;
    for (int idx = tid; idx < DD * DD; idx += blockDim.x) {
        int v;
        if (mode == 2)      v = (((const float*)mb)[idx] != 0.0f);
        else if (mode == 1) v = (mb[idx] != 0);
        else                v = (((const int*)mb)[idx] != 0);
        g_mask[idx] = v;
    }
}

// ---------------------------------------------------------------------------
// Decoder W-prep: masked dec1_w -> fp16, layout [n][k].
// ---------------------------------------------------------------------------
__global__ void wprep_kernel(const float* __restrict__ w1g) {
    int i = blockIdx.x, tid = threadIdx.x;
    unsigned char* wb = g_wbf + (size_t)i * 32768;
    for (int idx = tid; idx < DD * HID; idx += blockDim.x) {
        int k = idx >> 8, n = idx & 255;
        float m = (float)g_mask[k * DD + i];
        float w = w1g[(size_t)i * DD * HID + (size_t)k * HID + n] * m;
        *(__half*)(wb + n * 128 + k * 2) = __float2half_rn(w);
    }
}

// ---------------------------------------------------------------------------
// Encoder W-prep: enc1_w -> [n][k]; enc3_w -> [n][k]. fp16.
// ---------------------------------------------------------------------------
__global__ void ewprep_kernel(const float* __restrict__ w1,
                              const float* __restrict__ w2) {
    int t = blockIdx.x * 256 + threadIdx.x;
    int stride = gridDim.x * 256;
    for (int idx = t; idx < 64 * 256; idx += stride) {
        int n = idx >> 6, k = idx & 63;
        *(__half*)(g_ew1 + n * 128 + k * 2) = __float2half_rn(w1[k * 256 + n]);
    }
    for (int idx = t; idx < 256 * 128; idx += stride) {
        int n = idx >> 8, k = idx & 255;
        *(__half*)(g_ew2 + n * 512 + k * 2) = __float2half_rn(w2[k * 128 + n]);
    }
}

// ---------------------------------------------------------------------------
// Output transpose: g_gout[i][row] -> outX[row][i], outYr[row][i] (+zeros).
// Fully coalesced both sides; smem 64x65 tile (conflict-free).
// ---------------------------------------------------------------------------
__global__ __launch_bounds__(256) void out_tr_kernel(float* __restrict__ outX,
                                                     float* __restrict__ outYr) {
    __shared__ float ts[64][65];
    int tid = threadIdx.x;
    size_t row0 = (size_t)blockIdx.x * 64;
    int tx = tid & 63, ty = tid >> 6;
#pragma unroll
    for (int i = ty; i < 64; i += 4)
        ts[i][tx] = g_gout[(size_t)i * BATCH + row0 + tx];
    __syncthreads();
#pragma unroll
    for (int r = ty; r < 64; r += 4) {
        size_t row = row0 + r;
        float v = ts[tx][r];
        outX[row * 64 + tx] = v;
        outYr[row * 128 + tx] = v;
        outYr[row * 128 + 64 + tx] = 0.f;
    }
}

// ---------------------------------------------------------------------------
// Tensor-core fused encoder (R16, unchanged; x staged directly from fp32).
// ---------------------------------------------------------------------------
#define E_SB1 0
#define E_SB2 1024
#define E_SW1 1536
#define E_SW2 38400
#define E_SX  105984
#define E_SH  142848

__global__ __launch_bounds__(256, 1)
void enc_mma_kernel(const float* __restrict__ x,
                    const float* __restrict__ eps,
                    const float* __restrict__ b1g,
                    const float* __restrict__ b2g,
                    float* __restrict__ outMu,
                    float* __restrict__ outLv) {
    uint32_t sb = smem_u32(smemraw);
    float* sB1e = (float*)(smemraw + E_SB1);
    float* sB2e = (float*)(smemraw + E_SB2);
    int tid = threadIdx.x, wid = tid >> 5, lane = tid & 31;
    int row0 = blockIdx.x * 256;
    int r8 = lane & 7, g = lane >> 3;
    int mt = wid & 3, nh = wid >> 2;
    int cq = (lane & 3) * 2, rq = lane >> 2;

    sB1e[tid] = b1g[tid];
    if (tid < 128) sB2e[tid] = b2g[tid];
#pragma unroll
    for (int c = 0; c < 8; c++)
        cp_async16(sb + E_SW1 + tid * 144 + c * 16, g_ew1 + tid * 128 + c * 16);
#pragma unroll
    for (int c = 0; c < 16; c++)
        cp_async16(sb + E_SW2 + (tid >> 1) * 528 + (tid & 1) * 256 + c * 16,
                   g_ew2 + (tid >> 1) * 512 + (tid & 1) * 256 + c * 16);
    CP_COMMIT();
    {
        const float4* xr = (const float4*)(x + (size_t)(row0 + tid) * 64);
#pragma unroll
        for (int c = 0; c < 16; c++) {
            float4 v = xr[c];
            __half2 a = __floats2half2_rn(v.x, v.y);
            __half2 b = __floats2half2_rn(v.z, v.w);
            *(uint32_t*)(smemraw + E_SX + tid * 144 + c * 8)     = *(uint32_t*)&a;
            *(uint32_t*)(smemraw + E_SX + tid * 144 + c * 8 + 4) = *(uint32_t*)&b;
        }
    }
    CP_WAIT0();
    __syncthreads();

    for (int sbk = 0; sbk < 4; sbk++) {
        if (sbk) __syncthreads();

        float acc1[16][4];
#pragma unroll
        for (int t = 0; t < 16; t++)
#pragma unroll
            for (int q = 0; q < 4; q++) acc1[t][q] = 0.f;
        {
            uint32_t aBase = sb + E_SX + (uint32_t)(sbk * 64 + mt * 16 + (g & 1) * 8 + r8) * 144
                             + (uint32_t)((g >> 1) * 16);
            uint32_t bBase = sb + E_SW1 + (uint32_t)(nh * 128 + (g >> 1) * 8 + r8) * 144
                             + (uint32_t)((g & 1) * 16);
#pragma unroll
            for (int ks = 0; ks < 4; ks++) {
                uint32_t Ah[4];
                ldsm_x4(aBase + ks * 32, Ah[0], Ah[1], Ah[2], Ah[3]);
#pragma unroll
                for (int tp = 0; tp < 8; tp++) {
                    uint32_t Bq[4];
                    ldsm_x4(bBase + tp * 16 * 144 + ks * 32, Bq[0], Bq[1], Bq[2], Bq[3]);
                    mma16816(acc1[tp * 2], Ah, Bq[0], Bq[1]);
                    mma16816(acc1[tp * 2 + 1], Ah, Bq[2], Bq[3]);
                }
            }
        }
#pragma unroll
        for (int nt = 0; nt < 16; nt++) {
            int col = nh * 128 + nt * 8 + cq;
            float b1a = sB1e[col], b1b = sB1e[col + 1];
            int row = mt * 16 + rq;
            __half2 h01 = __floats2half2_rn(fmaxf(acc1[nt][0] + b1a, 0.f),
                                            fmaxf(acc1[nt][1] + b1b, 0.f));
            __half2 h23 = __floats2half2_rn(fmaxf(acc1[nt][2] + b1a, 0.f),
                                            fmaxf(acc1[nt][3] + b1b, 0.f));
            *(__half2*)(smemraw + E_SH + row * 528 + col * 2) = h01;
            *(__half2*)(smemraw + E_SH + (row + 8) * 528 + col * 2) = h23;
        }
        __syncthreads();

        float acc2[8][4];
#pragma unroll
        for (int t = 0; t < 8; t++)
#pragma unroll
            for (int q = 0; q < 4; q++) acc2[t][q] = 0.f;
        {
            uint32_t aBase = sb + E_SH + (uint32_t)(mt * 16 + (g & 1) * 8 + r8) * 528
                             + (uint32_t)((g >> 1) * 16);
            uint32_t bBase = sb + E_SW2 + (uint32_t)(nh * 64 + (g >> 1) * 8 + r8) * 528
                             + (uint32_t)((g & 1) * 16);
#pragma unroll
            for (int ks = 0; ks < 16; ks++) {
                uint32_t Ah[4];
                ldsm_x4(aBase + ks * 32, Ah[0], Ah[1], Ah[2], Ah[3]);
#pragma unroll
                for (int tp = 0; tp < 4; tp++) {
                    uint32_t Bq[4];
                    ldsm_x4(bBase + tp * 16 * 528 + ks * 32, Bq[0], Bq[1], Bq[2], Bq[3]);
                    mma16816(acc2[tp * 2], Ah, Bq[0], Bq[1]);
                    mma16816(acc2[tp * 2 + 1], Ah, Bq[2], Bq[3]);
                }
            }
        }
        __syncthreads();
#pragma unroll
        for (int nt = 0; nt < 8; nt++) {
            int col = nh * 64 + nt * 8 + cq;
            float b2a = sB2e[col], b2b = sB2e[col + 1];
            int row = mt * 16 + rq;
            *(float2*)(smemraw + E_SH + row * 528 + col * 4) =
                make_float2(acc2[nt][0] + b2a, acc2[nt][1] + b2b);
            *(float2*)(smemraw + E_SH + (row + 8) * 528 + col * 4) =
                make_float2(acc2[nt][2] + b2a, acc2[nt][3] + b2b);
        }
        __syncthreads();

        for (int idx = tid; idx < 64 * 64; idx += 256) {
            int r = idx >> 6, c = idx & 63;
            size_t rowAbs = (size_t)row0 + sbk * 64 + r;
            float mu = *(const float*)(smemraw + E_SH + r * 528 + c * 4);
            float lv = *(const float*)(smemraw + E_SH + r * 528 + (64 + c) * 4);
            float e = eps[rowAbs * DD + c];
            float ey = mu + expf(lv * 0.5f) * e;
            outMu[rowAbs * DD + c] = mu;
            outLv[rowAbs * DD + c] = lv;
            *(__half*)(g_abf + rowAbs * 128 + c * 2) = __float2half_rn(ey);
        }
    }
}

// ---------------------------------------------------------------------------
// Decoder v9 = R16 with split dacc chains + coalesced transposed output.
// smem: sB1h half2[128] @0, psum[2][256][4] @2048, A0 @10240 (256x144),
//       A1 @47104; W' staged transiently at A0. Total 83968 B, 2 CTAs/SM.
// ---------------------------------------------------------------------------
#define RP_A  144
#define SW_OFF  10240
#define SA0_OFF 10240
#define SA1_OFF 47104
#define PSUM_OFF 2048

__global__ __launch_bounds__(256, 2)
void dec_mma_kernel(const float* __restrict__ b1g,
                    const float* __restrict__ w3g,
                    const float* __restrict__ b3g) {
    uint32_t sb = smem_u32(smemraw);
    __half2* sB1h = (__half2*)smemraw;            // 128 half2
    float* psum = (float*)(smemraw + PSUM_OFF);   // [2][256][4]
    int tid = threadIdx.x, wid = tid >> 5, lane = tid & 31;
    int i = blockIdx.x;
    int tile0 = blockIdx.y * 16;
    int nc = wid & 3, rh = wid >> 2;
    const int kmax = (i >> 4) + 1;
    const int kc2 = 2 * kmax;

    // ---- stage W' fp16 + packed b1 ----
    {
        const unsigned char* src = g_wbf + (size_t)i * 32768;
#pragma unroll
        for (int c = 0; c < 8; c++)
            if (c < kc2)
                cp_async16(sb + SW_OFF + tid * RP_A + c * 16, src + tid * 128 + c * 16);
        CP_COMMIT();
        if (tid < 128)
            sB1h[tid] = __floats2half2_rn(b1g[i * HID + 2 * tid], b1g[i * HID + 2 * tid + 1]);
    }
    float b3v = b3g[i];

    // ---- build this warp's w3 B-fragments (col 0 = w3, cols 1..7 = 0) ----
    uint32_t w3f[4][2];
#pragma unroll
    for (int ks2 = 0; ks2 < 4; ks2++) { w3f[ks2][0] = 0u; w3f[ks2][1] = 0u; }
    if ((lane >> 2) == 0) {
#pragma unroll
        for (int ks2 = 0; ks2 < 4; ks2++) {
            int k0 = nc * 64 + ks2 * 16 + (lane & 3) * 2;
            __half2 lo = __floats2half2_rn(w3g[i * HID + k0], w3g[i * HID + k0 + 1]);
            __half2 hi = __floats2half2_rn(w3g[i * HID + k0 + 8], w3g[i * HID + k0 + 9]);
            w3f[ks2][0] = *(uint32_t*)&lo;
            w3f[ks2][1] = *(uint32_t*)&hi;
        }
    }
    CP_WAIT0();
    __syncthreads();

    // ---- load this warp's main-GEMM B fragments into registers ----
    int r8 = lane & 7, g = lane >> 3;
    uint32_t Bh[4][16];
#pragma unroll
    for (int ks = 0; ks < 4; ks++)
#pragma unroll
        for (int q = 0; q < 16; q++) Bh[ks][q] = 0u;
    {
        uint32_t bRow = (uint32_t)((g >> 1) * 8 + r8);
        uint32_t bCol = (uint32_t)((g & 1) * 16);
        uint32_t bBase = sb + SW_OFF + (uint32_t)(nc * 64 + bRow) * RP_A + bCol;
#pragma unroll
        for (int ks = 0; ks < 4; ks++) {
            if (ks < kmax) {
#pragma unroll
                for (int tp = 0; tp < 4; tp++) {
                    uint32_t a = bBase + tp * 16 * RP_A + ks * 32;
                    ldsm_x4(a, Bh[ks][tp * 4], Bh[ks][tp * 4 + 1],
                            Bh[ks][tp * 4 + 2], Bh[ks][tp * 4 + 3]);
                }
            }
        }
    }
    __syncthreads();   // W' region free; A buffers may reuse it

    // ---- prefetch A tile 0 ----
    {
        const unsigned char* src = g_abf + (size_t)tile0 * 256 * 128;
#pragma unroll
        for (int c = 0; c < 8; c++)
            if (c < kc2)
                cp_async16(sb + SA0_OFF + tid * RP_A + c * 16, src + tid * 128 + c * 16);
        CP_COMMIT();
    }

    uint32_t aRowBase = (uint32_t)(rh * 128 + (g & 1) * 8 + r8);
    uint32_t aCol = (uint32_t)((g >> 1) * 16);
    int rq = lane >> 2;
    uint32_t b1addr = sb + (uint32_t)((lane & 3) * 4) + (uint32_t)(nc * 128);
    float* gout = g_gout + (size_t)i * BATCH;

    for (int j = 0; j < 16; j++) {
        CP_WAIT0();
        __syncthreads();
        int buf = j & 1;
        if (j + 1 < 16) {
            const unsigned char* src = g_abf + (size_t)(tile0 + j + 1) * 256 * 128;
            uint32_t dstOff = buf ? SA0_OFF : SA1_OFF;
#pragma unroll
            for (int c = 0; c < 8; c++)
                if (c < kc2)
                    cp_async16(sb + dstOff + tid * RP_A + c * 16, src + tid * 128 + c * 16);
            CP_COMMIT();
        }

        uint32_t aTile = sb + (buf ? SA1_OFF : SA0_OFF);
#pragma unroll 1
        for (int mb = 0; mb < 8; mb++) {
            uint32_t aBase = aTile + (aRowBase + mb * 16) * RP_A + aCol;
            float acc[8][4];
#pragma unroll
            for (int t = 0; t < 8; t++)
#pragma unroll
                for (int q = 0; q < 4; q++) acc[t][q] = 0.f;

#pragma unroll
            for (int ks = 0; ks < 4; ks++) {
                if (ks < kmax) {
                    uint32_t Ah[4];
                    ldsm_x4(aBase + ks * 32, Ah[0], Ah[1], Ah[2], Ah[3]);
#pragma unroll
                    for (int nt = 0; nt < 8; nt++)
                        mma16816(acc[nt], Ah, Bh[ks][nt * 2], Bh[ks][nt * 2 + 1]);
                }
            }

            // ---- epilogue: relu(acc+b1) fp16 -> dot(w3), TWO independent
            // 2-deep MMA chains (halved serial latency) ----
            float dA[4] = {0.f, 0.f, 0.f, 0.f};
            float dB[4] = {0.f, 0.f, 0.f, 0.f};
#pragma unroll
            for (int ks2 = 0; ks2 < 4; ks2++) {
                uint32_t Af[4];
#pragma unroll
                for (int h = 0; h < 2; h++) {
                    int nt = 2 * ks2 + h;
                    uint32_t b1p;
                    asm("ld.shared.b32 %0, [%1];" : "=r"(b1p)
                        : "r"(b1addr + (uint32_t)(nt * 16)));
                    uint32_t p0, p1;
                    asm("cvt.rn.f16x2.f32 %0, %1, %2;" : "=r"(p0)
                        : "f"(acc[nt][1]), "f"(acc[nt][0]));
                    asm("cvt.rn.f16x2.f32 %0, %1, %2;" : "=r"(p1)
                        : "f"(acc[nt][3]), "f"(acc[nt][2]));
                    asm("add.rn.f16x2 %0, %0, %1;" : "+r"(p0) : "r"(b1p));
                    asm("add.rn.f16x2 %0, %0, %1;" : "+r"(p1) : "r"(b1p));
                    asm("max.f16x2 %0, %0, %1;" : "+r"(p0) : "r"(0u));
                    asm("max.f16x2 %0, %0, %1;" : "+r"(p1) : "r"(0u));
                    Af[2 * h] = p0;
                    Af[2 * h + 1] = p1;
                }
                if (ks2 < 2) mma16816(dA, Af, w3f[ks2][0], w3f[ks2][1]);
                else         mma16816(dB, Af, w3f[ks2][0], w3f[ks2][1]);
            }
            if ((lane & 3) == 0) {
                int row = rh * 128 + mb * 16 + rq;
                psum[buf * 1024 + row * 4 + nc] = dA[0] + dB[0];
                psum[buf * 1024 + (row + 8) * 4 + nc] = dA[2] + dB[2];
            }
        }
        __syncthreads();
        {
            float o = psum[buf * 1024 + tid * 4 + 0] + psum[buf * 1024 + tid * 4 + 1] +
                      psum[buf * 1024 + tid * 4 + 2] + psum[buf * 1024 + tid * 4 + 3] + b3v;
            gout[(size_t)(tile0 + j) * 256 + tid] = o;   // coalesced
        }
    }
}

// ---------------------------------------------------------------------------
extern "C" void kernel_launch(void* const* d_in, const int* in_sizes, int n_in,
                              void* d_out, int out_size) {
    const float* x      = (const float*)d_in[0];
    const float* eps    = (const float*)d_in[1];
    const float* enc1_w = (const float*)d_in[2];
    const float* enc1_b = (const float*)d_in[3];
    const float* enc3_w = (const float*)d_in[4];
    const float* enc3_b = (const float*)d_in[5];
    const float* dec1_w = (const float*)d_in[6];
    const float* dec1_b = (const float*)d_in[7];
    const float* dec3_w = (const float*)d_in[8];
    const float* dec3_b = (const float*)d_in[9];
    const unsigned char* bmask = (const unsigned char*)d_in[10];
    (void)n_in; (void)in_sizes; (void)out_size;

    float* out   = (float*)d_out;
    float* outX  = out;
    float* outMu = out + (size_t)BATCH * DD;
    float* outLv = out + (size_t)2 * BATCH * DD;
    float* outYr = out + (size_t)3 * BATCH * DD;

    size_t sEnc = 176640;
    size_t sDec = 83968;
    cudaFuncSetAttribute(enc_mma_kernel, cudaFuncAttributeMaxDynamicSharedMemorySize, (int)sEnc);
    cudaFuncSetAttribute(dec_mma_kernel, cudaFuncAttributeMaxDynamicSharedMemorySize, (int)sDec);

    mask_expand_kernel<<<1, 256>>>(bmask);
    wprep_kernel<<<DD, 256>>>(dec1_w);
    ewprep_kernel<<<32, 256>>>(enc1_w, enc3_w);
    enc_mma_kernel<<<BATCH / 256, 256, sEnc>>>(x, eps, enc1_b, enc3_b, outMu, outLv);
    dec_mma_kernel<<<dim3(DD, NT256 / 16), 256, sDec>>>(dec1_b, dec3_w, dec3_b);
    out_tr_kernel<<<BATCH / 64, 256>>>(outX, outYr);
}